// round 13
// baseline (speedup 1.0000x reference)
#include <cuda_runtime.h>

// CTC forward loss. B=32, T=1000, V=1024, L=100, S=2L+1=201.
//
// Pass 1: g_emit[b][t][s] = pred[b][t][ext[s]] + EPS (linear; 0 if invalid).
// Pass 2: linear-domain DP, 2 steps per barrier via redundant neighbor
//   recompute through shared memory. R13 fix vs R12: the emission window
//   buffers are TWO named register arrays (erA/erB) with compile-time
//   indices only -- R12's er[c][j] (dynamic c) was demoted to local memory,
//   adding ~380 cyc of LDL/STL per window. Main loop unrolled 2 windows.
//   Exact 2^k block rescale every 2 windows (target 2^120), IEEE ops.
// Mean-reduce fused.

#define Bc 32
#define Tc 1000
#define Vc 1024
#define Lc 100
#define Sc 201
#define EPSV (1e-7f)
#define NTHREADS 224
#define ESTR 224
#define ASZ (NTHREADS + 8)    // lane s at [s+4]; [0..3] zero pad
#define LN2F 0.6931471805599453f

__device__ float    g_emit[(size_t)Bc * Tc * ESTR];   // ~28.7 MB scratch
__device__ float    g_loss[Bc];
__device__ unsigned g_done;                           // zero-init; atomicInc wraps

__device__ __forceinline__ float lg2f_(float x) { float y; asm("lg2.approx.ftz.f32 %0, %1;" : "=f"(y) : "f"(x)); return y; }

// ---------------- Pass 1: emission gather (parallel, linear) ----------------
__global__ __launch_bounds__(NTHREADS)
void ctc_emit_kernel(const float* __restrict__ pred,
                     const int*   __restrict__ lenA,
                     const int*   __restrict__ lenB,
                     const int*   __restrict__ labels)
{
    const int t = blockIdx.x;
    const int b = blockIdx.y;
    const int s = threadIdx.x;

    const int la = lenA[b], lb = lenB[b];
    const int ilen = min(max(max(la, lb), 1), Tc);
    const int llen = min(max(min(la, lb), 1), Lc);
    if (t >= ilen) return;

    int ext = Vc - 1;
    if ((s & 1) && s < Sc) ext = labels[b * Lc + (s >> 1)] & (Vc - 1);

    const bool valid = (s < Sc) && (s < 2 * llen + 1);
    const float p = pred[((size_t)b * Tc + t) * Vc + ext];
    g_emit[((size_t)b * Tc + t) * ESTR + s] = valid ? (p + EPSV) : 0.0f;
}

// allow-skip coefficient for extended lane x (1.0 iff odd, labels differ)
__device__ __forceinline__ float allow_at(int x, const int* lab, int b)
{
    if (x < 1 || x >= Sc || !(x & 1)) return 0.0f;
    if (x == 1) return 1.0f;
    const int e0 = lab[b * Lc + (x >> 1)]     & (Vc - 1);
    const int e1 = lab[b * Lc + (x >> 1) - 1] & (Vc - 1);
    return (e0 != e1) ? 1.0f : 0.0f;
}

// ---------------- Pass 2: serial DP, 2 steps per barrier ----------------
__global__ __launch_bounds__(NTHREADS, 1)
void ctc_dp_kernel(const int* __restrict__ lenA,
                   const int* __restrict__ lenB,
                   const int* __restrict__ labels,
                   float*     __restrict__ out)
{
    __shared__ float    alpha[2][ASZ];
    __shared__ unsigned red[7];

    const int b = blockIdx.x;
    const int s = threadIdx.x;

    const int la = lenA[b], lb = lenB[b];
    const int ilen = min(max(max(la, lb), 1), Tc);
    const int llen = min(max(min(la, lb), 1), Lc);

    const float al0 = allow_at(s,     labels, b);
    const float al1 = allow_at(s - 1, labels, b);
    const float al2 = allow_at(s - 2, labels, b);

    const float* ebs  = g_emit + (size_t)b * Tc * ESTR + s;
    const float* ebs1 = g_emit + (size_t)b * Tc * ESTR + max(s - 1, 0);
    const float* ebs2 = g_emit + (size_t)b * Tc * ESTR + max(s - 2, 0);
    // (clamped cols feed nodes whose alpha inputs are all 0 -> product is 0)

    // zero both buffers (pads included)
    alpha[0][s] = 0.0f;  alpha[1][s] = 0.0f;
    if (s < ASZ - NTHREADS) {
        alpha[0][NTHREADS + s] = 0.0f;
        alpha[1][NTHREADS + s] = 0.0f;
    }
    __syncthreads();

    // ---- t = 0 (emit pass already zeroed invalid lanes) ----
    alpha[0][s + 4] = (s < 2) ? ebs[0] : 0.0f;

    // ---- preload windows A (t=1,2) and B (t=3,4): all constant indices ----
    float erA0, erA1, erA2, erA3, erB0, erB1, erB2, erB3;
    {
        const int tA0 = min(1, Tc - 1), tA1 = min(2, Tc - 1);
        const int tB0 = min(3, Tc - 1), tB1 = min(4, Tc - 1);
        erA0 = ebs [(size_t)tA0 * ESTR];
        erA1 = ebs [(size_t)tA1 * ESTR];
        erA2 = ebs1[(size_t)tA0 * ESTR];
        erA3 = ebs2[(size_t)tA0 * ESTR];
        erB0 = ebs [(size_t)tB0 * ESTR];
        erB1 = ebs [(size_t)tB1 * ESTR];
        erB2 = ebs1[(size_t)tB0 * ESTR];
        erB3 = ebs2[(size_t)tB0 * ESTR];
    }
    __syncthreads();

    int   t = 1, cur = 0;
    int   Ktot = 0, kPend = 0;
    float pend1 = 1.0f, pend2 = 1.0f;     // neutral first application (exact)

    // ---- main loop: 2 windows (4 steps) per iteration ----
    while (t + 4 <= ilen) {
        // ======== window A: steps t, t+1 (applies pending rescale) ========
        {
            const float a0 = alpha[cur][s + 4];
            const float a1 = alpha[cur][s + 3];
            const float a2 = alpha[cur][s + 2];
            const float a3 = alpha[cur][s + 1];
            const float a4 = alpha[cur][s + 0];

            const float A0 = __fmul_rn(__fmaf_rn(al0, a2, __fadd_rn(a0, a1)), erA0);
            const float A1 = __fmul_rn(__fmaf_rn(al1, a3, __fadd_rn(a1, a2)), erA2);
            const float A2 = __fmul_rn(__fmaf_rn(al2, a4, __fadd_rn(a2, a3)), erA3);
            float nv = __fmul_rn(__fmaf_rn(al0, A2, __fadd_rn(A0, A1)), erA1);
            nv = __fmul_rn(__fmul_rn(nv, pend1), pend2);
            Ktot += kPend;

            // prefetch window t+4 into erA (constant register names)
            {
                const int t0 = min(t + 4, Tc - 1), t1 = min(t + 5, Tc - 1);
                erA0 = ebs [(size_t)t0 * ESTR];
                erA1 = ebs [(size_t)t1 * ESTR];
                erA2 = ebs1[(size_t)t0 * ESTR];
                erA3 = ebs2[(size_t)t0 * ESTR];
            }

            alpha[cur ^ 1][s + 4] = nv;
            __syncthreads();
            cur ^= 1;
        }

        // ======== window B: steps t+2, t+3 (computes next rescale) ========
        {
            const float a0 = alpha[cur][s + 4];
            const float a1 = alpha[cur][s + 3];
            const float a2 = alpha[cur][s + 2];
            const float a3 = alpha[cur][s + 1];
            const float a4 = alpha[cur][s + 0];

            const float A0 = __fmul_rn(__fmaf_rn(al0, a2, __fadd_rn(a0, a1)), erB0);
            const float A1 = __fmul_rn(__fmaf_rn(al1, a3, __fadd_rn(a1, a2)), erB2);
            const float A2 = __fmul_rn(__fmaf_rn(al2, a4, __fadd_rn(a2, a3)), erB3);
            const float nv = __fmul_rn(__fmaf_rn(al0, A2, __fadd_rn(A0, A1)), erB1);

            // prefetch window t+6 into erB
            {
                const int t0 = min(t + 6, Tc - 1), t1 = min(t + 7, Tc - 1);
                erB0 = ebs [(size_t)t0 * ESTR];
                erB1 = ebs [(size_t)t1 * ESTR];
                erB2 = ebs1[(size_t)t0 * ESTR];
                erB3 = ebs2[(size_t)t0 * ESTR];
            }

            alpha[cur ^ 1][s + 4] = nv;

            // block max (nv >= 0: uint order == float order)
            const unsigned mv = __reduce_max_sync(0xffffffffu, __float_as_uint(nv));
            if ((s & 31) == 0) red[s >> 5] = mv;
            __syncthreads();

            unsigned M = red[0];
            #pragma unroll
            for (int ww = 1; ww < 7; ++ww) M = max(M, red[ww]);
            const int ee = (int)((M >> 23) & 0xFFu);
            kPend = 247 - ee;                       // rescale target 2^120
            const int k1 = kPend >> 1;
            pend1 = __uint_as_float((unsigned)(127 + k1) << 23);
            pend2 = __uint_as_float((unsigned)(127 + (kPend - k1)) << 23);

            cur ^= 1;
        }

        t += 4;
    }

    // ---- tail: up to 3 steps, direct emission loads ----
    {
        bool first = true;
        for (; t < ilen; ++t) {
            const float e0 = ebs [(size_t)t * ESTR];
            const float a0 = alpha[cur][s + 4];
            const float a1 = alpha[cur][s + 3];
            const float a2 = alpha[cur][s + 2];
            float nv = __fmul_rn(__fmaf_rn(al0, a2, __fadd_rn(a0, a1)), e0);
            if (first) {
                nv = __fmul_rn(__fmul_rn(nv, pend1), pend2);
                Ktot += kPend;
                first = false;
            }
            alpha[cur ^ 1][s + 4] = nv;
            __syncthreads();
            cur ^= 1;
        }
        // if tail empty, last-computed rescale was never applied and Ktot
        // was never incremented -> consistent, nothing to do.
    }

    // ---- finalize; fused mean ----
    if (s == 0) {
        const float a1f = alpha[cur][2 * llen - 1 + 4];
        const float a2f = alpha[cur][2 * llen + 4];
        const float ll  = (lg2f_(__fadd_rn(a1f, a2f)) - (float)Ktot) * LN2F;
        g_loss[b] = -ll;

        __threadfence();
        const unsigned old = atomicInc(&g_done, Bc - 1);
        if (old == Bc - 1) {
            __threadfence();
            float acc = 0.0f;
            #pragma unroll
            for (int i = 0; i < Bc; ++i) acc += g_loss[i];
            out[0] = acc * (1.0f / (float)Bc);
        }
    }
}

extern "C" void kernel_launch(void* const* d_in, const int* in_sizes, int n_in,
                              void* d_out, int out_size)
{
    // Identify inputs by size rank (robust to ordering / bytes-vs-elems).
    int idx[4] = {0, 1, 2, 3};
    for (int i = 0; i < 3; ++i)
        for (int j = i + 1; j < 4; ++j)
            if ((long long)in_sizes[idx[j]] > (long long)in_sizes[idx[i]]) {
                int tmp = idx[i]; idx[i] = idx[j]; idx[j] = tmp;
            }

    const float* pred   = (const float*)d_in[idx[0]];  // [B,T,V]
    const int*   labels = (const int*)  d_in[idx[1]];  // [B,L]
    const int*   lenA   = (const int*)  d_in[idx[2]];  // length vectors
    const int*   lenB   = (const int*)  d_in[idx[3]];

    float* out = (float*)d_out;

    dim3 g1(Tc, Bc);
    ctc_emit_kernel<<<g1, NTHREADS>>>(pred, lenA, lenB, labels);
    ctc_dp_kernel<<<Bc, NTHREADS>>>(lenA, lenB, labels, out);
}

// round 14
// speedup vs baseline: 1.3596x; 1.3596x over previous
#include <cuda_runtime.h>

// CTC forward loss. B=32, T=1000, V=1024, L=100, S=2L+1=201.
//
// Pass 1: g_emit[b][t][s] = pred[b][t][ext[s]] + EPS (linear; 0 if invalid).
// Pass 2: linear-domain DP, 1 step/barrier (R10 skeleton -- empirically the
//   fastest structure), but TWO LANES PER THREAD held in REGISTERS:
//   even lanes have no skip transition, so the only cross-thread value is
//   a[2j-1] -> per step just 1 LDS.32 + 1 STS.32 + 1 LDG.64 (prefetched).
//   4 warps instead of 7. Exact 2^k rescale every 4 steps (target 2^120),
//   IEEE ops. Mean-reduce fused.

#define Bc 32
#define Tc 1000
#define Vc 1024
#define Lc 100
#define Sc 201
#define EPSV (1e-7f)
#define EMIT_NT 224
#define ESTR 224            // emission row stride in floats (112 float2)
#define DP_NT 128           // 4 warps; thread j owns lanes 2j, 2j+1
#define ASZ 258             // alpha idx: lane s at [s+2]
#define LN2F 0.6931471805599453f

__device__ float    g_emit[(size_t)Bc * Tc * ESTR];   // ~28.7 MB scratch
__device__ float    g_loss[Bc];
__device__ unsigned g_done;                           // zero-init; atomicInc wraps

__device__ __forceinline__ float lg2f_(float x) { float y; asm("lg2.approx.ftz.f32 %0, %1;" : "=f"(y) : "f"(x)); return y; }

// ---------------- Pass 1: emission gather (parallel, linear) ----------------
__global__ __launch_bounds__(EMIT_NT)
void ctc_emit_kernel(const float* __restrict__ pred,
                     const int*   __restrict__ lenA,
                     const int*   __restrict__ lenB,
                     const int*   __restrict__ labels)
{
    const int t = blockIdx.x;
    const int b = blockIdx.y;
    const int s = threadIdx.x;

    const int la = lenA[b], lb = lenB[b];
    const int ilen = min(max(max(la, lb), 1), Tc);
    const int llen = min(max(min(la, lb), 1), Lc);
    if (t >= ilen) return;

    int ext = Vc - 1;
    if ((s & 1) && s < Sc) ext = labels[b * Lc + (s >> 1)] & (Vc - 1);

    const bool valid = (s < Sc) && (s < 2 * llen + 1);
    const float p = pred[((size_t)b * Tc + t) * Vc + ext];
    g_emit[((size_t)b * Tc + t) * ESTR + s] = valid ? (p + EPSV) : 0.0f;
}

// ---------------- Pass 2: serial DP, 2 lanes/thread in registers ------------
__global__ __launch_bounds__(DP_NT, 1)
void ctc_dp_kernel(const int* __restrict__ lenA,
                   const int* __restrict__ lenB,
                   const int* __restrict__ labels,
                   float*     __restrict__ out)
{
    __shared__ float    alpha[2][ASZ];   // only odd lanes flow through smem
    __shared__ unsigned red[4];

    const int b  = blockIdx.x;
    const int j  = threadIdx.x;          // owns lanes s0=2j, s1=2j+1
    const int s1 = 2 * j + 1;

    const int la = lenA[b], lb = lenB[b];
    const int ilen = min(max(max(la, lb), 1), Tc);
    const int llen = min(max(min(la, lb), 1), Lc);

    // skip coefficient for the odd lane s1 (even lanes never skip)
    float al1 = 0.0f;
    if (s1 < Sc) {
        if (s1 == 1) al1 = 1.0f;
        else {
            const int e0 = labels[b * Lc + (s1 >> 1)]     & (Vc - 1);
            const int e1 = labels[b * Lc + (s1 >> 1) - 1] & (Vc - 1);
            al1 = (e0 != e1) ? 1.0f : 0.0f;
        }
    }

    // emission pair pointer (float2); clamp j>=112 (their lanes read zeros at 222/223)
    const float2* eb = (const float2*)g_emit + (size_t)b * Tc * (ESTR / 2) + min(j, ESTR / 2 - 1);

    // zero both alpha buffers
    for (int i = j; i < ASZ; i += DP_NT) { alpha[0][i] = 0.0f; alpha[1][i] = 0.0f; }
    __syncthreads();

    // ---- t = 0 ----
    float r0 = 0.0f, r1 = 0.0f;
    if (j == 0) { const float2 e = eb[0]; r0 = e.x; r1 = e.y; }
    alpha[0][2 * j + 3] = r1;            // seed odd-lane channel

    // ---- preload emission pairs for t = 1..8 ----
    float2 er[8];
    #pragma unroll
    for (int jj = 0; jj < 8; ++jj) {
        const int tn = min(1 + jj, Tc - 1);
        er[jj] = eb[(size_t)tn * (ESTR / 2)];
    }
    __syncthreads();

    int   cur = 0, t = 1;
    int   Ktot = 0, kPend = 0;
    float pend1 = 1.0f, pend2 = 1.0f;    // neutral first application (exact)

    // ---- main loop: 8 steps unrolled, 1 barrier/step ----
    while (t + 8 <= ilen) {
        #pragma unroll
        for (int jj = 0; jj < 8; ++jj) {
            // prefetch emission pair for step t+8+jj
            const int tn = min(t + 8 + jj, Tc - 1);
            const float2 pn = eb[(size_t)tn * (ESTR / 2)];

            const float n1 = alpha[cur][2 * j + 1];   // a[2j-1] from neighbor
            float nv0 = __fmul_rn(__fadd_rn(r0, n1), er[jj].x);
            float nv1 = __fmul_rn(__fmaf_rn(al1, n1, __fadd_rn(r1, r0)), er[jj].y);
            if (jj == 0 || jj == 4) {                 // apply pending rescale
                nv0 = __fmul_rn(__fmul_rn(nv0, pend1), pend2);
                nv1 = __fmul_rn(__fmul_rn(nv1, pend1), pend2);
                Ktot += kPend;
            }
            r0 = nv0; r1 = nv1;
            alpha[cur ^ 1][2 * j + 3] = r1;

            if (jj == 3 || jj == 7) {                 // block max (vals >= 0)
                unsigned mv = (j <= 100)
                            ? max(__float_as_uint(nv0), __float_as_uint(nv1)) : 0u;
                mv = __reduce_max_sync(0xffffffffu, mv);
                if ((j & 31) == 0) red[j >> 5] = mv;
            }
            __syncthreads();
            if (jj == 3 || jj == 7) {
                const unsigned M = max(max(red[0], red[1]), max(red[2], red[3]));
                const int ee = (int)((M >> 23) & 0xFFu);
                kPend = 247 - ee;                     // rescale target 2^120
                const int k1 = kPend >> 1;
                pend1 = __uint_as_float((unsigned)(127 + k1) << 23);
                pend2 = __uint_as_float((unsigned)(127 + (kPend - k1)) << 23);
            }
            cur ^= 1;
            er[jj] = pn;
        }
        t += 8;
    }

    // ---- tail (< 8 steps); constant-indexed, er already resident ----
    #pragma unroll
    for (int jj = 0; jj < 8; ++jj) {
        if (t + jj >= ilen) break;
        const float n1 = alpha[cur][2 * j + 1];
        float nv0 = __fmul_rn(__fadd_rn(r0, n1), er[jj].x);
        float nv1 = __fmul_rn(__fmaf_rn(al1, n1, __fadd_rn(r1, r0)), er[jj].y);
        if (jj == 0) {                                // apply pending rescale once
            nv0 = __fmul_rn(__fmul_rn(nv0, pend1), pend2);
            nv1 = __fmul_rn(__fmul_rn(nv1, pend1), pend2);
            Ktot += kPend;
        }
        r0 = nv0; r1 = nv1;
        alpha[cur ^ 1][2 * j + 3] = r1;
        __syncthreads();
        cur ^= 1;
    }
    // (empty tail: last-measured rescale never applied & never counted -- consistent)

    // ---- finalize: dump pairs, compute loss, fused mean ----
    alpha[cur][2 * j + 2] = r0;
    alpha[cur][2 * j + 3] = r1;
    __syncthreads();
    if (j == 0) {
        const float a1f = alpha[cur][2 * llen + 1];   // lane 2*llen-1
        const float a2f = alpha[cur][2 * llen + 2];   // lane 2*llen
        const float ll  = (lg2f_(__fadd_rn(a1f, a2f)) - (float)Ktot) * LN2F;
        g_loss[b] = -ll;

        __threadfence();
        const unsigned old = atomicInc(&g_done, Bc - 1);
        if (old == Bc - 1) {
            __threadfence();
            float acc = 0.0f;
            #pragma unroll
            for (int i = 0; i < Bc; ++i) acc += g_loss[i];
            out[0] = acc * (1.0f / (float)Bc);
        }
    }
}

extern "C" void kernel_launch(void* const* d_in, const int* in_sizes, int n_in,
                              void* d_out, int out_size)
{
    // Identify inputs by size rank (robust to ordering / bytes-vs-elems).
    int idx[4] = {0, 1, 2, 3};
    for (int i = 0; i < 3; ++i)
        for (int j = i + 1; j < 4; ++j)
            if ((long long)in_sizes[idx[j]] > (long long)in_sizes[idx[i]]) {
                int tmp = idx[i]; idx[i] = idx[j]; idx[j] = tmp;
            }

    const float* pred   = (const float*)d_in[idx[0]];  // [B,T,V]
    const int*   labels = (const int*)  d_in[idx[1]];  // [B,L]
    const int*   lenA   = (const int*)  d_in[idx[2]];  // length vectors
    const int*   lenB   = (const int*)  d_in[idx[3]];

    float* out = (float*)d_out;

    dim3 g1(Tc, Bc);
    ctc_emit_kernel<<<g1, EMIT_NT>>>(pred, lenA, lenB, labels);
    ctc_dp_kernel<<<Bc, DP_NT>>>(lenA, lenB, labels, out);
}